// round 15
// baseline (speedup 1.0000x reference)
#include <cuda_runtime.h>
#include <cuda_fp16.h>
#include <cstdint>

#define VOCAB 100000
#define EMB   128
#define NTOK  (4096 * 200)
#define NTILE 3125           // VOCAB / 32

// 25.6 MB scratch: pre-normalized fp16 table [VOCAB, EMB]. Row = 256B.
__device__ __half g_table[(size_t)VOCAB * EMB];

// 256-bit loads/stores (sm_103: L2 evict hints require .v8.b32 form).
__device__ __forceinline__ void st256_evict_last(void* p, const uint32_t* u) {
    asm volatile("st.global.L2::evict_last.v8.b32 [%0], {%1,%2,%3,%4,%5,%6,%7,%8};"
                 :: "l"(p),
                    "r"(u[0]), "r"(u[1]), "r"(u[2]), "r"(u[3]),
                    "r"(u[4]), "r"(u[5]), "r"(u[6]), "r"(u[7])
                 : "memory");
}
__device__ __forceinline__ void ld256(const void* p, uint32_t* u) {
    asm volatile("ld.global.nc.v8.b32 {%0,%1,%2,%3,%4,%5,%6,%7}, [%8];"
                 : "=r"(u[0]), "=r"(u[1]), "=r"(u[2]), "=r"(u[3]),
                   "=r"(u[4]), "=r"(u[5]), "=r"(u[6]), "=r"(u[7])
                 : "l"(p));
}
__device__ __forceinline__ void ld256_evict_last(const void* p, uint32_t* u) {
    asm volatile("ld.global.nc.L2::evict_last.v8.b32 {%0,%1,%2,%3,%4,%5,%6,%7}, [%8];"
                 : "=r"(u[0]), "=r"(u[1]), "=r"(u[2]), "=r"(u[3]),
                   "=r"(u[4]), "=r"(u[5]), "=r"(u[6]), "=r"(u[7])
                 : "l"(p));
}
__device__ __forceinline__ void st256_evict_first(void* p, const uint32_t* u) {
    asm volatile("st.global.L2::evict_first.v8.b32 [%0], {%1,%2,%3,%4,%5,%6,%7,%8};"
                 :: "l"(p),
                    "r"(u[0]), "r"(u[1]), "r"(u[2]), "r"(u[3]),
                    "r"(u[4]), "r"(u[5]), "r"(u[6]), "r"(u[7])
                 : "memory");
}

// ---------------------------------------------------------------------------
// Kernel 1: fused transpose + bias + L2-normalize -> fp16 table.
// Pipelined: each block handles 2 vocab-tiles; tile B's W loads are issued
// while tile A is reduced and written, hiding one DRAM latency per pair.
// Conflict-free smem (tile[v][e], 32x129) in all phases.
// Grid: ceil(NTILE/2) = 1563 blocks, 256 threads.
// ---------------------------------------------------------------------------
__global__ void __launch_bounds__(256) transpose_norm_kernel(
    const float* __restrict__ W,
    const float* __restrict__ bias)
{
    __shared__ float tile[32][129];   // [v][e], +1 pad (129 % 32 == 1)
    __shared__ float bsm[128];
    __shared__ float inv[32];

    const int tid  = threadIdx.x;
    const int wid  = tid >> 5;
    const int lane = tid & 31;

    if (tid < 128) bsm[tid] = bias[tid];

    // This thread's two fill chunks (512 chunks of 32B per tile).
    const int e0c = tid >> 2,          q0 = tid & 3;
    const int e1c = (tid + 256) >> 2,  q1 = (tid + 256) & 3;

    const int  t0    = blockIdx.x * 2;          // first tile index
    const long base0 = (long)t0 * 32;           // vocab offset of tile A
    const bool has2  = (t0 + 1) < NTILE;

    // Issue tile A loads.
    uint32_t a0[8], a1[8];
    ld256(&W[(size_t)e0c * VOCAB + base0 + q0 * 8], a0);
    ld256(&W[(size_t)e1c * VOCAB + base0 + q1 * 8], a1);

    uint32_t b0[8], b1[8];

    // ---------------- tile A ----------------
#pragma unroll
    for (int k = 0; k < 8; k++) tile[q0 * 8 + k][e0c] = __uint_as_float(a0[k]);
#pragma unroll
    for (int k = 0; k < 8; k++) tile[q1 * 8 + k][e1c] = __uint_as_float(a1[k]);
    __syncthreads();

    // Prefetch tile B while tile A is processed.
    if (has2) {
        const long base1 = base0 + 32;
        ld256(&W[(size_t)e0c * VOCAB + base1 + q0 * 8], b0);
        ld256(&W[(size_t)e1c * VOCAB + base1 + q1 * 8], b1);
    }

    // Reduce A: 8 warps x 4 vocab rows.
#pragma unroll
    for (int j = 0; j < 4; j++) {
        const int v = wid * 4 + j;
        float s = 0.f;
#pragma unroll
        for (int k = 0; k < 4; k++) {
            const int e = lane + k * 32;
            const float t = tile[v][e] + bsm[e];
            s += t * t;
        }
#pragma unroll
        for (int off = 16; off; off >>= 1)
            s += __shfl_xor_sync(0xffffffffu, s, off);
        if (lane == 0)
            inv[v] = 1.0f / fmaxf(sqrtf(s), 1e-12f);
    }
    __syncthreads();

    // Write A: warp w owns emb chunk [16w,16w+16); lane = vocab row.
    {
        const int e0 = wid * 16;
        const float iv = inv[lane];
        uint32_t u[8];
#pragma unroll
        for (int k = 0; k < 8; k++) {
            float2 f;
            f.x = (tile[lane][e0 + 2 * k + 0] + bsm[e0 + 2 * k + 0]) * iv;
            f.y = (tile[lane][e0 + 2 * k + 1] + bsm[e0 + 2 * k + 1]) * iv;
            __half2 h = __float22half2_rn(f);
            u[k] = *reinterpret_cast<uint32_t*>(&h);
        }
        st256_evict_last(&g_table[(size_t)(base0 + lane) * EMB + e0], u);
    }

    if (!has2) return;

    // ---------------- tile B ----------------
    __syncthreads();    // everyone done reading tile A's smem
#pragma unroll
    for (int k = 0; k < 8; k++) tile[q0 * 8 + k][e0c] = __uint_as_float(b0[k]);
#pragma unroll
    for (int k = 0; k < 8; k++) tile[q1 * 8 + k][e1c] = __uint_as_float(b1[k]);
    __syncthreads();

#pragma unroll
    for (int j = 0; j < 4; j++) {
        const int v = wid * 4 + j;
        float s = 0.f;
#pragma unroll
        for (int k = 0; k < 4; k++) {
            const int e = lane + k * 32;
            const float t = tile[v][e] + bsm[e];
            s += t * t;
        }
#pragma unroll
        for (int off = 16; off; off >>= 1)
            s += __shfl_xor_sync(0xffffffffu, s, off);
        if (lane == 0)
            inv[v] = 1.0f / fmaxf(sqrtf(s), 1e-12f);
    }
    __syncthreads();

    {
        const long base1 = base0 + 32;
        const int e0 = wid * 16;
        const float iv = inv[lane];
        uint32_t u[8];
#pragma unroll
        for (int k = 0; k < 8; k++) {
            float2 f;
            f.x = (tile[lane][e0 + 2 * k + 0] + bsm[e0 + 2 * k + 0]) * iv;
            f.y = (tile[lane][e0 + 2 * k + 1] + bsm[e0 + 2 * k + 1]) * iv;
            __half2 h = __float22half2_rn(f);
            u[k] = *reinterpret_cast<uint32_t*>(&h);
        }
        st256_evict_last(&g_table[(size_t)(base1 + lane) * EMB + e0], u);
    }
}

// ---------------------------------------------------------------------------
// Kernel 2: gather fp16 rows -> f32 output. 8 tokens/warp. (At its write-path
// ceiling: ~74% DRAM across all tried variants — unchanged.)
// ---------------------------------------------------------------------------
__global__ void __launch_bounds__(256) gather_kernel(
    const int* __restrict__ x,
    float* __restrict__ out)
{
    const int warp  = (blockIdx.x * 256 + threadIdx.x) >> 5;
    const int lane  = threadIdx.x & 31;
    const int t0    = warp * 8;           // 8 consecutive tokens per warp
    const int group = lane >> 3;          // which of 4 tokens in this load
    const int off   = lane & 7;           // 32B chunk within the 256B row

    const int4 ia = __ldg(&reinterpret_cast<const int4*>(x)[warp * 2 + 0]);
    const int4 ib = __ldg(&reinterpret_cast<const int4*>(x)[warp * 2 + 1]);
    const int ga[4] = {ia.x, ia.y, ia.z, ia.w};
    const int gb[4] = {ib.x, ib.y, ib.z, ib.w};
    const int ta = ga[group];
    const int tb = gb[group];

    // 2 independent loads; each fetches 1KB warp-wide = 4 complete rows.
    uint32_t ua[8], ub[8];
    ld256_evict_last(&g_table[(size_t)ta * EMB + off * 16], ua);
    ld256_evict_last(&g_table[(size_t)tb * EMB + off * 16], ub);

    // Convert 16 halves -> 16 floats and store 64B per lane (2 x 32B).
    uint32_t fa[16], fb[16];
#pragma unroll
    for (int k = 0; k < 8; k++) {
        float2 f = __half22float2(*reinterpret_cast<__half2*>(&ua[k]));
        fa[2 * k + 0] = __float_as_uint(f.x);
        fa[2 * k + 1] = __float_as_uint(f.y);
        f = __half22float2(*reinterpret_cast<__half2*>(&ub[k]));
        fb[2 * k + 0] = __float_as_uint(f.x);
        fb[2 * k + 1] = __float_as_uint(f.y);
    }

    float* oa = out + (size_t)(t0 + group) * EMB + off * 16;
    float* ob = out + (size_t)(t0 + 4 + group) * EMB + off * 16;
    st256_evict_first(oa + 0, fa);
    st256_evict_first(oa + 8, fa + 8);
    st256_evict_first(ob + 0, fb);
    st256_evict_first(ob + 8, fb + 8);
}

// ---------------------------------------------------------------------------
extern "C" void kernel_launch(void* const* d_in, const int* in_sizes, int n_in,
                              void* d_out, int out_size) {
    const int*   x = (const int*)d_in[0];   // [4096, 200] int32
    const float* W = (const float*)d_in[1]; // [128, 100000] f32
    const float* b = (const float*)d_in[2]; // [128] f32
    float* out = (float*)d_out;             // [4096, 200, 128] f32

    // 1) Build pre-normalized fp16 table (pipelined, 2 tiles/block)
    const int nblk1 = (NTILE + 1) / 2;      // 1563
    transpose_norm_kernel<<<nblk1, 256>>>(W, b);

    // 2) Gather: 8 tokens/warp, 8 warps/block
    const int nwarps  = NTOK / 8;           // 102400
    const int nblocks = nwarps / 8;         // 12800
    gather_kernel<<<nblocks, 256>>>(x, out);
}

// round 16
// speedup vs baseline: 1.0312x; 1.0312x over previous
#include <cuda_runtime.h>
#include <cuda_fp16.h>
#include <cstdint>

#define VOCAB 100000
#define EMB   128
#define NTOK  (4096 * 200)

// 25.6 MB scratch: pre-normalized fp16 table [VOCAB, EMB]. Row = 256B.
__device__ __half g_table[(size_t)VOCAB * EMB];

// 256-bit loads/stores (sm_103: L2 evict hints require .v8.b32 form).
__device__ __forceinline__ void st256_evict_last(void* p, const uint32_t* u) {
    asm volatile("st.global.L2::evict_last.v8.b32 [%0], {%1,%2,%3,%4,%5,%6,%7,%8};"
                 :: "l"(p),
                    "r"(u[0]), "r"(u[1]), "r"(u[2]), "r"(u[3]),
                    "r"(u[4]), "r"(u[5]), "r"(u[6]), "r"(u[7])
                 : "memory");
}
__device__ __forceinline__ void ld256(const void* p, uint32_t* u) {
    asm volatile("ld.global.nc.v8.b32 {%0,%1,%2,%3,%4,%5,%6,%7}, [%8];"
                 : "=r"(u[0]), "=r"(u[1]), "=r"(u[2]), "=r"(u[3]),
                   "=r"(u[4]), "=r"(u[5]), "=r"(u[6]), "=r"(u[7])
                 : "l"(p));
}
__device__ __forceinline__ void ld256_evict_last(const void* p, uint32_t* u) {
    asm volatile("ld.global.nc.L2::evict_last.v8.b32 {%0,%1,%2,%3,%4,%5,%6,%7}, [%8];"
                 : "=r"(u[0]), "=r"(u[1]), "=r"(u[2]), "=r"(u[3]),
                   "=r"(u[4]), "=r"(u[5]), "=r"(u[6]), "=r"(u[7])
                 : "l"(p));
}
__device__ __forceinline__ void st256_evict_first(void* p, const uint32_t* u) {
    asm volatile("st.global.L2::evict_first.v8.b32 [%0], {%1,%2,%3,%4,%5,%6,%7,%8};"
                 :: "l"(p),
                    "r"(u[0]), "r"(u[1]), "r"(u[2]), "r"(u[3]),
                    "r"(u[4]), "r"(u[5]), "r"(u[6]), "r"(u[7])
                 : "memory");
}

// ---------------------------------------------------------------------------
// Kernel 1: fused transpose + bias + L2-normalize -> fp16 table.
// One tile (32 vocab entries) per block, grid 3125 (max inter-block overlap;
// the 2-tile pipelined variant regressed). Both 256-bit W loads are issued
// before any smem scatter (MLP=2 on the fill). Conflict-free smem
// (tile[v][e], 32x129) in all phases.
// ---------------------------------------------------------------------------
__global__ void __launch_bounds__(256) transpose_norm_kernel(
    const float* __restrict__ W,
    const float* __restrict__ bias)
{
    __shared__ float tile[32][129];   // [v][e], +1 pad (129 % 32 == 1)
    __shared__ float bsm[128];
    __shared__ float inv[32];

    const int tid  = threadIdx.x;
    const int wid  = tid >> 5;
    const int lane = tid & 31;
    const int v0   = blockIdx.x * 32;

    if (tid < 128) bsm[tid] = bias[tid];

    // Fill: 512 chunks of 32B; thread handles chunks tid and tid+256.
    // Both loads in flight before either scatter.
    const int e0c = tid >> 2,          q0 = tid & 3;
    const int e1c = (tid + 256) >> 2,  q1 = (tid + 256) & 3;
    uint32_t a0[8], a1[8];
    ld256(&W[(size_t)e0c * VOCAB + v0 + q0 * 8], a0);
    ld256(&W[(size_t)e1c * VOCAB + v0 + q1 * 8], a1);
#pragma unroll
    for (int k = 0; k < 8; k++) tile[q0 * 8 + k][e0c] = __uint_as_float(a0[k]);
#pragma unroll
    for (int k = 0; k < 8; k++) tile[q1 * 8 + k][e1c] = __uint_as_float(a1[k]);
    __syncthreads();

    // Reduce: 8 warps x 4 vocab rows; lane sums 4 strided elements.
#pragma unroll
    for (int j = 0; j < 4; j++) {
        const int v = wid * 4 + j;
        float s = 0.f;
#pragma unroll
        for (int k = 0; k < 4; k++) {
            const int e = lane + k * 32;
            const float t = tile[v][e] + bsm[e];
            s += t * t;
        }
#pragma unroll
        for (int off = 16; off; off >>= 1)
            s += __shfl_xor_sync(0xffffffffu, s, off);
        if (lane == 0)
            inv[v] = 1.0f / fmaxf(sqrtf(s), 1e-12f);
    }
    __syncthreads();

    // Write: warp w owns emb-chunk [16w, 16w+16); lane = vocab row.
    {
        const int e0 = wid * 16;
        const float iv = inv[lane];
        uint32_t u[8];
#pragma unroll
        for (int k = 0; k < 8; k++) {
            float2 f;
            f.x = (tile[lane][e0 + 2 * k + 0] + bsm[e0 + 2 * k + 0]) * iv;
            f.y = (tile[lane][e0 + 2 * k + 1] + bsm[e0 + 2 * k + 1]) * iv;
            __half2 h = __float22half2_rn(f);
            u[k] = *reinterpret_cast<uint32_t*>(&h);
        }
        st256_evict_last(&g_table[(size_t)(v0 + lane) * EMB + e0], u);
    }
}

// ---------------------------------------------------------------------------
// Kernel 2: gather fp16 rows -> f32 output. 8 tokens/warp. (At its write-path
// ceiling: ~74% DRAM across all tried variants — unchanged.)
// ---------------------------------------------------------------------------
__global__ void __launch_bounds__(256) gather_kernel(
    const int* __restrict__ x,
    float* __restrict__ out)
{
    const int warp  = (blockIdx.x * 256 + threadIdx.x) >> 5;
    const int lane  = threadIdx.x & 31;
    const int t0    = warp * 8;           // 8 consecutive tokens per warp
    const int group = lane >> 3;          // which of 4 tokens in this load
    const int off   = lane & 7;           // 32B chunk within the 256B row

    const int4 ia = __ldg(&reinterpret_cast<const int4*>(x)[warp * 2 + 0]);
    const int4 ib = __ldg(&reinterpret_cast<const int4*>(x)[warp * 2 + 1]);
    const int ga[4] = {ia.x, ia.y, ia.z, ia.w};
    const int gb[4] = {ib.x, ib.y, ib.z, ib.w};
    const int ta = ga[group];
    const int tb = gb[group];

    // 2 independent loads; each fetches 1KB warp-wide = 4 complete rows.
    uint32_t ua[8], ub[8];
    ld256_evict_last(&g_table[(size_t)ta * EMB + off * 16], ua);
    ld256_evict_last(&g_table[(size_t)tb * EMB + off * 16], ub);

    // Convert 16 halves -> 16 floats and store 64B per lane (2 x 32B).
    uint32_t fa[16], fb[16];
#pragma unroll
    for (int k = 0; k < 8; k++) {
        float2 f = __half22float2(*reinterpret_cast<__half2*>(&ua[k]));
        fa[2 * k + 0] = __float_as_uint(f.x);
        fa[2 * k + 1] = __float_as_uint(f.y);
        f = __half22float2(*reinterpret_cast<__half2*>(&ub[k]));
        fb[2 * k + 0] = __float_as_uint(f.x);
        fb[2 * k + 1] = __float_as_uint(f.y);
    }

    float* oa = out + (size_t)(t0 + group) * EMB + off * 16;
    float* ob = out + (size_t)(t0 + 4 + group) * EMB + off * 16;
    st256_evict_first(oa + 0, fa);
    st256_evict_first(oa + 8, fa + 8);
    st256_evict_first(ob + 0, fb);
    st256_evict_first(ob + 8, fb + 8);
}

// ---------------------------------------------------------------------------
extern "C" void kernel_launch(void* const* d_in, const int* in_sizes, int n_in,
                              void* d_out, int out_size) {
    const int*   x = (const int*)d_in[0];   // [4096, 200] int32
    const float* W = (const float*)d_in[1]; // [128, 100000] f32
    const float* b = (const float*)d_in[2]; // [128] f32
    float* out = (float*)d_out;             // [4096, 200, 128] f32

    // 1) Build pre-normalized fp16 table (1 tile/block, grid 3125)
    transpose_norm_kernel<<<VOCAB / 32, 256>>>(W, b);

    // 2) Gather: 8 tokens/warp, 8 warps/block
    const int nwarps  = NTOK / 8;           // 102400
    const int nblocks = nwarps / 8;         // 12800
    gather_kernel<<<nblocks, 256>>>(x, out);
}